// round 8
// baseline (speedup 1.0000x reference)
#include <cuda_runtime.h>
#include <cuda_bf16.h>
#include <cstdint>

#define Bsz 256
#define Ssz 256
#define Esz 256
#define Hsz 1024
#define G4  4096   // 4*H

// ---- step kernel tiling: 4 warps, warp tile M64xN32, CTA M64xN128 ----
#define BMt 64                  // M tile (batch rows per CTA)
#define HT  32                  // h columns per gate per CTA
#define NT  128                 // N tile = 4 gates * HT
#define KC  64                  // K chunk (bf16 elements = 128 B row)
#define NCHUNK (Hsz / KC)       // 16
#define NSTAGE 3

// ---- smem layout ----
#define A_MAT_BYTES (BMt * KC * 2)                      // 8 KB per matrix
#define B_MAT_BYTES (NT * KC * 2)                       // 16 KB per matrix
#define STAGE_BYTES (2 * A_MAT_BYTES + 2 * B_MAT_BYTES) // 48 KB
#define OFF_AHI 0
#define OFF_ALO (A_MAT_BYTES)
#define OFF_BHI (2 * A_MAT_BYTES)
#define OFF_BLO (2 * A_MAT_BYTES + B_MAT_BYTES)
#define SMEM_TOTAL (NSTAGE * STAGE_BYTES)               // 144 KB (L1D keeps ~84 KB)
#define DPITCH 132

// ---- device globals (no allocation allowed) ----
__device__ float g_letter_proj[30 * G4];
__device__ float g_state_proj[4 * G4];
__device__ __nv_bfloat16 g_W_hi[(size_t)G4 * Hsz];   // 8 MB
__device__ __nv_bfloat16 g_W_lo[(size_t)G4 * Hsz];   // 8 MB
__device__ __nv_bfloat16 g_h_hi[2][Bsz * Hsz];
__device__ __nv_bfloat16 g_h_lo[2][Bsz * Hsz];
__device__ float g_c[2][Bsz * Hsz];

// ---------------------------------------------------------------------------
// PTX helpers
// ---------------------------------------------------------------------------
__device__ __forceinline__ uint32_t smem_u32(const void* p) {
    uint32_t a;
    asm("{ .reg .u64 t; cvta.to.shared.u64 t, %1; cvt.u32.u64 %0, t; }"
        : "=r"(a) : "l"(p));
    return a;
}
__device__ __forceinline__ void cp16(uint32_t s, const void* g) {
    asm volatile("cp.async.cg.shared.global [%0], [%1], 16;"
                 :: "r"(s), "l"(g) : "memory");
}
#define CP_COMMIT() asm volatile("cp.async.commit_group;" ::: "memory")
#define CP_WAIT1()  asm volatile("cp.async.wait_group 1;" ::: "memory")

__device__ __forceinline__ void ldsm4(uint32_t a, uint32_t* r) {
    asm volatile("ldmatrix.sync.aligned.m8n8.x4.shared.b16 {%0,%1,%2,%3}, [%4];"
                 : "=r"(r[0]), "=r"(r[1]), "=r"(r[2]), "=r"(r[3]) : "r"(a));
}
__device__ __forceinline__ void mma16816(float* c, const uint32_t* a,
                                         const uint32_t* b) {
    asm volatile(
        "mma.sync.aligned.m16n8k16.row.col.f32.bf16.bf16.f32 "
        "{%0,%1,%2,%3}, {%4,%5,%6,%7}, {%8,%9}, {%0,%1,%2,%3};"
        : "+f"(c[0]), "+f"(c[1]), "+f"(c[2]), "+f"(c[3])
        : "r"(a[0]), "r"(a[1]), "r"(a[2]), "r"(a[3]), "r"(b[0]), "r"(b[1]));
}
__device__ __forceinline__ float sigmoidf_(float x) {
    return 1.0f / (1.0f + expf(-x));
}

// ---------------------------------------------------------------------------
// One-time prep: split W_hh into bf16 hi/lo
// ---------------------------------------------------------------------------
__global__ void wsplit_kernel(const float* __restrict__ W) {
    size_t i = ((size_t)blockIdx.x * blockDim.x + threadIdx.x) * 4;
    float4 w = *(const float4*)(W + i);
    float v[4] = {w.x, w.y, w.z, w.w};
    #pragma unroll
    for (int j = 0; j < 4; j++) {
        __nv_bfloat16 hi = __float2bfloat16(v[j]);
        g_W_hi[i + j] = hi;
        g_W_lo[i + j] = __float2bfloat16(v[j] - __bfloat162float(hi));
    }
}

// ---------------------------------------------------------------------------
// One-time prep: x_proj lookup tables (incl. biases), plain [gate*H + h]
// ---------------------------------------------------------------------------
__global__ void proj_kernel(const float* __restrict__ letter_emb,
                            const float* __restrict__ state_emb,
                            const float* __restrict__ W_ih,
                            const float* __restrict__ b_ih,
                            const float* __restrict__ b_hh) {
    int tok  = blockIdx.y;
    int g    = blockIdx.x * 8 + (threadIdx.x >> 5);
    int lane = threadIdx.x & 31;

    const float* emb;
    const float* w;
    if (tok < 30) {
        emb = letter_emb + tok * Esz;
        w   = W_ih + (size_t)g * (2 * Esz);
    } else {
        emb = state_emb + (tok - 30) * Esz;
        w   = W_ih + (size_t)g * (2 * Esz) + Esz;
    }

    float acc = 0.f;
    for (int k = lane; k < Esz; k += 32)
        acc += emb[k] * w[k];
    #pragma unroll
    for (int off = 16; off; off >>= 1)
        acc += __shfl_xor_sync(0xFFFFFFFFu, acc, off);

    if (lane == 0) {
        if (tok < 30)
            g_letter_proj[tok * G4 + g] = acc + b_ih[g] + b_hh[g];
        else
            g_state_proj[(tok - 30) * G4 + g] = acc;
    }
}

// ---------------------------------------------------------------------------
// HMMA LSTM step. grid (32, 4) = 128 CTAs, 128 threads (4 warps).
// Warp tile M64 x N32 (25% less LDSM traffic than 32x32).
// D = Ahi*Bhi + Alo*Bhi + Ahi*Blo (fp32 accum). 3-stage cp.async pipeline,
// fragment double-buffering across ks to hide LDSM latency (1 warp/SMSP).
// ---------------------------------------------------------------------------
__global__ void __launch_bounds__(128, 1)
lstm_step_mma(const int* __restrict__ letter_seq,
              const int* __restrict__ state_seq,
              float* __restrict__ out_h,
              float* __restrict__ out_c,
              int s) {
    extern __shared__ char smem[];
    const uint32_t smem_base = smem_u32(smem);

    const int tid = threadIdx.x;
    const int h0  = blockIdx.x * HT;
    const int bm0 = blockIdx.y * BMt;
    const int rbuf = (s & 1) ^ 1;
    const int wbuf = s & 1;

    const int wn = tid >> 5;          // 0..3: warp owns n cols [wn*32, wn*32+32)
    const int l  = tid & 31;

    // acc[mf][nq][4]: mf = m16 frag (0..3), nq = x*2 + n8-half
    float acc[4][4][4];
    #pragma unroll
    for (int i = 0; i < 4; i++)
        #pragma unroll
        for (int j = 0; j < 4; j++)
            #pragma unroll
            for (int k = 0; k < 4; k++)
                acc[i][j][k] = 0.f;

    if (s > 0) {
        // ---- stage-load constants (128 threads cover 48 KB/stage) ----
        // A (hi+lo): 64 rows x 8 granules: thread t -> row t>>1, granules (t&1)*4..+3
        const int ar  = tid >> 1;
        const int agb = (tid & 1) * 4;
        const __nv_bfloat16* hh = g_h_hi[rbuf] + (size_t)(bm0 + ar) * Hsz;
        const __nv_bfloat16* hl = g_h_lo[rbuf] + (size_t)(bm0 + ar) * Hsz;
        // B (hi+lo): 128 rows x 8 granules: thread t -> row t, all 8 granules
        const int bn = tid;                       // B smem row = gate*32 + hc
        const size_t wrow = (size_t)((bn >> 5) * Hsz + h0 + (bn & 31)) * Hsz;

        auto load_stage = [&](int ch) {
            const int k0 = ch * KC;
            const uint32_t sb = smem_base
                              + (uint32_t)(ch % NSTAGE) * STAGE_BYTES;
            #pragma unroll
            for (int j = 0; j < 4; j++) {
                int g = agb + j;
                uint32_t so = (uint32_t)ar * 128
                            + (uint32_t)(((g ^ (ar & 7)) & 7) * 16);
                cp16(sb + OFF_AHI + so, hh + k0 + g * 8);
                cp16(sb + OFF_ALO + so, hl + k0 + g * 8);
            }
            #pragma unroll
            for (int g = 0; g < 8; g++) {
                uint32_t so = (uint32_t)bn * 128
                            + (uint32_t)(((g ^ (bn & 7)) & 7) * 16);
                cp16(sb + OFF_BHI + so, g_W_hi + wrow + k0 + g * 8);
                cp16(sb + OFF_BLO + so, g_W_lo + wrow + k0 + g * 8);
            }
        };

        // ---- ldmatrix lane constants ----
        const int a_r0 = (l & 7) + ((l >> 3) & 1) * 8;   // + mf*16
        const int a_kh = l >> 4;
        const int b_n0 = wn * 32 + (l & 7) + (l >> 4) * 8; // + x*16
        const int b_kh = (l >> 3) & 1;

        // fragment double buffers across ks
        uint32_t ah[2][4][4], al[2][4][4], bh[2][2][4], bl[2][2][4];

        auto ldfrag = [&](int fb, uint32_t sb, int ks) {
            const int agq = ks * 2 + a_kh;
            const int bgq = ks * 2 + b_kh;
            #pragma unroll
            for (int mf = 0; mf < 4; mf++) {
                int r = a_r0 + mf * 16;
                uint32_t arow = (uint32_t)r * 128
                              + (uint32_t)((agq ^ (r & 7)) * 16);
                ldsm4(sb + OFF_AHI + arow, ah[fb][mf]);
                ldsm4(sb + OFF_ALO + arow, al[fb][mf]);
            }
            #pragma unroll
            for (int x = 0; x < 2; x++) {
                int n = b_n0 + x * 16;
                uint32_t brow = (uint32_t)n * 128
                              + (uint32_t)((bgq ^ (n & 7)) * 16);
                ldsm4(sb + OFF_BHI + brow, bh[fb][x]);
                ldsm4(sb + OFF_BLO + brow, bl[fb][x]);
            }
        };
        auto mma_all = [&](int fb) {
            // term-major: each acc quad revisited at distance 8+
            #pragma unroll
            for (int mf = 0; mf < 4; mf++)
                #pragma unroll
                for (int x = 0; x < 2; x++) {
                    mma16816(acc[mf][x * 2],     ah[fb][mf], &bh[fb][x][0]);
                    mma16816(acc[mf][x * 2 + 1], ah[fb][mf], &bh[fb][x][2]);
                }
            #pragma unroll
            for (int mf = 0; mf < 4; mf++)
                #pragma unroll
                for (int x = 0; x < 2; x++) {
                    mma16816(acc[mf][x * 2],     al[fb][mf], &bh[fb][x][0]);
                    mma16816(acc[mf][x * 2 + 1], al[fb][mf], &bh[fb][x][2]);
                }
            #pragma unroll
            for (int mf = 0; mf < 4; mf++)
                #pragma unroll
                for (int x = 0; x < 2; x++) {
                    mma16816(acc[mf][x * 2],     ah[fb][mf], &bl[fb][x][0]);
                    mma16816(acc[mf][x * 2 + 1], ah[fb][mf], &bl[fb][x][2]);
                }
        };

        load_stage(0); CP_COMMIT();
        load_stage(1); CP_COMMIT();

        for (int ch = 0; ch < NCHUNK; ch++) {
            CP_WAIT1();
            __syncthreads();
            if (ch + 2 < NCHUNK) load_stage(ch + 2);
            CP_COMMIT();

            const uint32_t sb = smem_base
                              + (uint32_t)(ch % NSTAGE) * STAGE_BYTES;
            ldfrag(0, sb, 0);
            #pragma unroll
            for (int ks = 0; ks < 4; ks++) {
                if (ks < 3) ldfrag((ks + 1) & 1, sb, ks + 1);
                mma_all(ks & 1);
            }
        }

        // ---- dump accums to smem D[64][DPITCH] ----
        __syncthreads();
        float* Dsm = (float*)smem;
        #pragma unroll
        for (int mf = 0; mf < 4; mf++)
            #pragma unroll
            for (int nf = 0; nf < 4; nf++) {
                int m = mf * 16 + (l >> 2);
                int n = wn * 32 + nf * 8 + (l & 3) * 2;
                *(float2*)&Dsm[m * DPITCH + n] =
                    make_float2(acc[mf][nf][0], acc[mf][nf][1]);
                *(float2*)&Dsm[(m + 8) * DPITCH + n] =
                    make_float2(acc[mf][nf][2], acc[mf][nf][3]);
            }
        __syncthreads();
    }

    // ---- fused LSTM cell epilogue: thread -> (m, 16 h-cols) ----
    {
        const float* Dsm = (const float*)smem;
        const int m    = tid >> 1;         // 0..63
        const int half = tid & 1;          // 16-col half
        const int b    = bm0 + m;
        const int lt = letter_seq[b * Ssz + s];
        const int st = state_seq[b * Ssz + s];
        const float* lp = g_letter_proj + (size_t)lt * G4 + h0;
        const float* sp = g_state_proj  + (size_t)st * G4 + h0;
        const size_t base  = (size_t)b * (Ssz * Hsz) + (size_t)s * Hsz + h0;
        const size_t cbase = (size_t)b * Hsz + h0;
        const int hl0 = half * 16;

        float hv[16], cv[16];
        #pragma unroll
        for (int j = 0; j < 16; j++) {
            const int hlc = hl0 + j;
            float pi, pf, pg, po;
            if (s > 0) {
                pi = Dsm[m * DPITCH + 0 * 32 + hlc];
                pf = Dsm[m * DPITCH + 1 * 32 + hlc];
                pg = Dsm[m * DPITCH + 2 * 32 + hlc];
                po = Dsm[m * DPITCH + 3 * 32 + hlc];
            } else {
                pi = pf = pg = po = 0.f;
            }
            pi += lp[hlc]           + sp[hlc];
            pf += lp[Hsz + hlc]     + sp[Hsz + hlc];
            pg += lp[2 * Hsz + hlc] + sp[2 * Hsz + hlc];
            po += lp[3 * Hsz + hlc] + sp[3 * Hsz + hlc];
            float cprev = (s > 0) ? g_c[rbuf][cbase + hlc] : 0.f;
            float c = sigmoidf_(pf) * cprev + sigmoidf_(pi) * tanhf(pg);
            cv[j] = c;
            hv[j] = sigmoidf_(po) * tanhf(c);
        }
        #pragma unroll
        for (int j = 0; j < 4; j++) {
            *(float4*)(out_h + base + hl0 + j * 4) =
                make_float4(hv[j*4], hv[j*4+1], hv[j*4+2], hv[j*4+3]);
            *(float4*)(out_c + base + hl0 + j * 4) =
                make_float4(cv[j*4], cv[j*4+1], cv[j*4+2], cv[j*4+3]);
            *(float4*)(g_c[wbuf] + cbase + hl0 + j * 4) =
                make_float4(cv[j*4], cv[j*4+1], cv[j*4+2], cv[j*4+3]);
        }
        __nv_bfloat162 dh[8], dl[8];
        #pragma unroll
        for (int j = 0; j < 8; j++) {
            float x0 = hv[2*j], x1 = hv[2*j+1];
            __nv_bfloat16 b0 = __float2bfloat16(x0);
            __nv_bfloat16 b1 = __float2bfloat16(x1);
            dh[j] = __nv_bfloat162(b0, b1);
            dl[j] = __nv_bfloat162(__float2bfloat16(x0 - __bfloat162float(b0)),
                                   __float2bfloat16(x1 - __bfloat162float(b1)));
        }
        *(uint4*)(g_h_hi[wbuf] + cbase + hl0)     = *(const uint4*)&dh[0];
        *(uint4*)(g_h_hi[wbuf] + cbase + hl0 + 8) = *(const uint4*)&dh[4];
        *(uint4*)(g_h_lo[wbuf] + cbase + hl0)     = *(const uint4*)&dl[0];
        *(uint4*)(g_h_lo[wbuf] + cbase + hl0 + 8) = *(const uint4*)&dl[4];
    }
}

// ---------------------------------------------------------------------------
extern "C" void kernel_launch(void* const* d_in, const int* in_sizes, int n_in,
                              void* d_out, int out_size) {
    const int*   letter_seq = (const int*)d_in[0];
    const int*   state_seq  = (const int*)d_in[1];
    const float* letter_emb = (const float*)d_in[2];
    const float* state_emb  = (const float*)d_in[3];
    const float* W_ih       = (const float*)d_in[4];
    const float* W_hh       = (const float*)d_in[5];
    const float* b_ih       = (const float*)d_in[6];
    const float* b_hh       = (const float*)d_in[7];

    float* out_h = (float*)d_out;
    float* out_c = out_h + (size_t)Bsz * Ssz * Hsz;

    static int smem_set = 0;
    if (!smem_set) {
        cudaFuncSetAttribute(lstm_step_mma,
                             cudaFuncAttributeMaxDynamicSharedMemorySize,
                             SMEM_TOTAL);
        smem_set = 1;
    }

    wsplit_kernel<<<(G4 * Hsz) / (256 * 4), 256>>>(W_hh);
    proj_kernel<<<dim3(G4 / 8, 34), 256>>>(letter_emb, state_emb, W_ih, b_ih, b_hh);

    for (int s = 0; s < Ssz; s++) {
        lstm_step_mma<<<dim3(Hsz / HT, Bsz / BMt), 128, SMEM_TOTAL>>>(
            letter_seq, state_seq, out_h, out_c, s);
    }
}